// round 17
// baseline (speedup 1.0000x reference)
#include <cuda_runtime.h>
#include <cuda_bf16.h>
#include <math.h>
#include <stdint.h>

// Problem constants
#define Bb     4
#define SEQ    2048
#define DIM    768
#define NH     12
#define DH     64
#define INNER  768
#define MROWS  (Bb * SEQ)   // 8192
#define NWF    (DIM * INNER)      // 589824 floats per weight

// Scratch (module-static device memory; allocation-free)
__device__ float g_wT[4 * NWF];               // tf32-rounded W^T: [n][k] per weight
__device__ __align__(16) __nv_bfloat16 g_qb[Bb * NH * SEQ * DH];  // *log2e/8
__device__ __align__(16) __nv_bfloat16 g_kb[Bb * NH * SEQ * DH];  // [b][h][n][dh]
__device__ __align__(16) __nv_bfloat16 g_vt[Bb * NH * DH * SEQ];  // [b][h][dh][n]
__device__ float g_att[MROWS * INNER];        // attention out (tf32), [b*n][h*64+dh]

// ---------------------------------------------------------------------------
// Helpers
// ---------------------------------------------------------------------------
__device__ __forceinline__ float tf32r(float x) {
    uint32_t u;
    asm("cvt.rna.tf32.f32 %0, %1;" : "=r"(u) : "f"(x));
    return __uint_as_float(u);
}

__device__ __forceinline__ void mma_tf32(float d[4], const uint32_t a[4],
                                         const uint32_t b[2]) {
    asm volatile(
        "mma.sync.aligned.m16n8k8.row.col.f32.tf32.tf32.f32 "
        "{%0,%1,%2,%3}, {%4,%5,%6,%7}, {%8,%9}, {%0,%1,%2,%3};"
        : "+f"(d[0]), "+f"(d[1]), "+f"(d[2]), "+f"(d[3])
        : "r"(a[0]), "r"(a[1]), "r"(a[2]), "r"(a[3]), "r"(b[0]), "r"(b[1]));
}

__device__ __forceinline__ void mma_bf16(float d[4], const uint32_t a[4],
                                         const uint32_t b[2]) {
    asm volatile(
        "mma.sync.aligned.m16n8k16.row.col.f32.bf16.bf16.f32 "
        "{%0,%1,%2,%3}, {%4,%5,%6,%7}, {%8,%9}, {%0,%1,%2,%3};"
        : "+f"(d[0]), "+f"(d[1]), "+f"(d[2]), "+f"(d[3])
        : "r"(a[0]), "r"(a[1]), "r"(a[2]), "r"(a[3]), "r"(b[0]), "r"(b[1]));
}

// Warp-collective: load 4 8x8 b16 matrices (= 4 8x4 u32 blocks for tf32).
__device__ __forceinline__ void ldmatrix_x4(uint32_t& r0, uint32_t& r1,
                                            uint32_t& r2, uint32_t& r3,
                                            uint32_t saddr) {
    asm volatile(
        "ldmatrix.sync.aligned.m8n8.x4.shared.b16 {%0,%1,%2,%3}, [%4];"
        : "=r"(r0), "=r"(r1), "=r"(r2), "=r"(r3) : "r"(saddr));
}

__device__ __forceinline__ uint32_t pack_bf16(float lo, float hi) {
    __nv_bfloat162 h = __floats2bfloat162_rn(lo, hi);
    return *(uint32_t*)&h;
}

__device__ __forceinline__ void cp16(uint32_t saddr, const void* gaddr) {
    asm volatile("cp.async.cg.shared.global [%0], [%1], 16;" :: "r"(saddr), "l"(gaddr));
}
#define CP_COMMIT()  asm volatile("cp.async.commit_group;")
#define CP_WAIT1()   asm volatile("cp.async.wait_group 1;" ::: "memory")
#define CP_WAIT0()   asm volatile("cp.async.wait_group 0;" ::: "memory")

// ---------------------------------------------------------------------------
// Kernel 0: round + TRANSPOSE the 4 weight matrices (32x32 smem tiles,
// coalesced in both directions).  g_wT[w][n][k] = tf32(W[k][n]).
// ---------------------------------------------------------------------------
__global__ void round_kernel(const float* __restrict__ Wq,
                             const float* __restrict__ Wk,
                             const float* __restrict__ Wv,
                             const float* __restrict__ Wp) {
    __shared__ float tile[32][33];
    const int w  = blockIdx.z;
    const int kb = blockIdx.y * 32;
    const int nb = blockIdx.x * 32;
    const float* src = (w == 0) ? Wq : (w == 1) ? Wk : (w == 2) ? Wv : Wp;
    const int tx = threadIdx.x & 31;
    const int ty = threadIdx.x >> 5;          // 0..7
#pragma unroll
    for (int i = 0; i < 4; i++) {
        const int k = kb + ty + i * 8;
        tile[ty + i * 8][tx] = tf32r(src[(size_t)k * INNER + nb + tx]);
    }
    __syncthreads();
    float* dst = g_wT + (size_t)w * NWF;
#pragma unroll
    for (int i = 0; i < 4; i++) {
        const int n = nb + ty + i * 8;
        dst[(size_t)n * DIM + kb + tx] = tile[tx][ty + i * 8];
    }
}

// ---------------------------------------------------------------------------
// GEMM smem geometry (qkv & proj): both operands K-major 128x32, stride 36,
// 3-stage cp.async.  A = activations [m][k], B = W^T [n][k].
// ---------------------------------------------------------------------------
#define KSTRIDE   36
#define STAGE     (128 * KSTRIDE)          // 4608 floats
#define BS_BASE   (3 * STAGE)              // 13824
#define GEMM_SMEM_FLOATS (6 * STAGE)       // 27648 -> 110592 B

// qkv epilogue staging overlay
#define STG_STRIDE 68

__device__ __forceinline__ void gemm_fill(uint32_t su, int st, int k0,
                                          const float* __restrict__ gA, int bm,
                                          const float* __restrict__ gBT, int bn,
                                          int t) {
#pragma unroll
    for (int i = 0; i < 4; i++) {
        const int lin = t + i * 256;       // 0..1023
        const int row = lin >> 3;
        const int ch  = lin & 7;
        cp16(su + (uint32_t)(st * STAGE + row * KSTRIDE + ch * 4) * 4,
             &gA[(size_t)(bm + row) * DIM + k0 + ch * 4]);
    }
#pragma unroll
    for (int i = 0; i < 4; i++) {
        const int lin = t + i * 256;
        const int row = lin >> 3;
        const int ch  = lin & 7;
        cp16(su + (uint32_t)(BS_BASE + st * STAGE + row * KSTRIDE + ch * 4) * 4,
             &gBT[(size_t)(bn + row) * DIM + k0 + ch * 4]);
    }
}

// ldmatrix-based compute: 6 ldmatrix.x4 + 16 mma per k8-step.
// a_off lane map: m0/m1 = rows +0/+8 at k-half 0; m2/m3 = rows +0/+8 at +4.
// b_off lane map: m0/m1 = k-halves 0/+4 of n-pair row group; m2/m3 = +8 rows.
__device__ __forceinline__ void gemm_compute(uint32_t su, int st,
                                             int m_base, int n_base,
                                             uint32_t a_off, uint32_t b_off,
                                             float acc[2][8][4]) {
    const uint32_t a_base = su + (uint32_t)(st * STAGE) * 4 + a_off;
    const uint32_t b_base = su + (uint32_t)((BS_BASE + st * STAGE)) * 4 + b_off;
#pragma unroll
    for (int ks = 0; ks < 4; ks++) {
        const int kk = ks * 8;
        uint32_t a[2][4];
#pragma unroll
        for (int mt = 0; mt < 2; mt++)
            ldmatrix_x4(a[mt][0], a[mt][1], a[mt][2], a[mt][3],
                        a_base + (uint32_t)((m_base + mt * 16) * KSTRIDE + kk) * 4);
#pragma unroll
        for (int jp = 0; jp < 4; jp++) {
            uint32_t b0, b1, b2, b3;
            ldmatrix_x4(b0, b1, b2, b3,
                        b_base + (uint32_t)((n_base + jp * 16) * KSTRIDE + kk) * 4);
            uint32_t br0[2] = {b0, b1};
            uint32_t br1[2] = {b2, b3};
#pragma unroll
            for (int mt = 0; mt < 2; mt++) {
                mma_tf32(acc[mt][2 * jp],     a[mt], br0);
                mma_tf32(acc[mt][2 * jp + 1], a[mt], br1);
            }
        }
    }
}

// A lane offset: row = (l&7) + ((l>>3)&1)*8, col-half = ((l>>4)&1)*4
// B lane offset: row = (l&7) + ((l>>4)&1)*8, col-half = ((l>>3)&1)*4
__device__ __forceinline__ uint32_t a_lane_off(int lane) {
    return (uint32_t)(((lane & 7) + ((lane >> 3) & 1) * 8) * KSTRIDE
                      + ((lane >> 4) & 1) * 4) * 4;
}
__device__ __forceinline__ uint32_t b_lane_off(int lane) {
    return (uint32_t)(((lane & 7) + ((lane >> 4) & 1) * 8) * KSTRIDE
                      + ((lane >> 3) & 1) * 4) * 4;
}

// ---------------------------------------------------------------------------
// Kernel 1: persistent fused QKV projection (tf32 MMA, ldmatrix frags),
// bf16 outputs with smem-staged coalesced stores.
// ---------------------------------------------------------------------------
#define QSCALE 0.1803368801111204f   // 0.125 * log2(e)
#define QKV_UNITS (3 * 64 * 6)       // 1152

__global__ __launch_bounds__(256, 2) void qkv_kernel(const float* __restrict__ x) {
    extern __shared__ float smf[];
    const uint32_t su = (uint32_t)__cvta_generic_to_shared(smf);
    uint32_t* stageu = (uint32_t*)smf;

    const int t  = threadIdx.x;
    const int warp = t >> 5;
    const int lane = t & 31;
    const int m_base = (warp >> 1) * 32;
    const int n_base = (warp & 1) * 64;
    const int qr = lane >> 2;
    const int qc = lane & 3;
    const uint32_t a_off = a_lane_off(lane);
    const uint32_t b_off = b_lane_off(lane);

    for (int unit = blockIdx.x; unit < QKV_UNITS; unit += gridDim.x) {
        __syncthreads();

        const int z      = unit / 384;
        const int rem    = unit - z * 384;
        const int bm     = (rem / 6) * 128;
        const int bn     = (rem % 6) * 128;

        const float* WT = g_wT + (size_t)z * NWF;
        __nv_bfloat16* outp = (z == 0) ? g_qb : (z == 1) ? g_kb : g_vt;
        const float scale = (z == 0) ? QSCALE : 1.0f;

        float acc[2][8][4];
#pragma unroll
        for (int mt = 0; mt < 2; mt++)
#pragma unroll
            for (int j = 0; j < 8; j++)
#pragma unroll
                for (int e = 0; e < 4; e++) acc[mt][j][e] = 0.0f;

        gemm_fill(su, 0, 0, x, bm, WT, bn, t);
        CP_COMMIT();
        gemm_fill(su, 1, 32, x, bm, WT, bn, t);
        CP_COMMIT();

        int cs = 0, fs = 2;
        for (int kt = 0; kt < DIM / 32; kt++) {
            if (kt + 1 < DIM / 32) { CP_WAIT1(); } else { CP_WAIT0(); }
            __syncthreads();
            if (kt + 2 < DIM / 32) {
                gemm_fill(su, fs, (kt + 2) * 32, x, bm, WT, bn, t);
                CP_COMMIT();
            }
            gemm_compute(su, cs, m_base, n_base, a_off, b_off, acc);
            cs = (cs == 2) ? 0 : cs + 1;
            fs = (fs == 2) ? 0 : fs + 1;
        }

        // ---- Epilogue: stage tile in smem (bf16 pairs), coalesced STG ----
        __syncthreads();
#pragma unroll
        for (int mt = 0; mt < 2; mt++) {
#pragma unroll
            for (int j = 0; j < 8; j++) {
                const int pr = (n_base + j * 8) / 2 + qc;
                const int r0 = m_base + mt * 16 + qr;
                stageu[r0 * STG_STRIDE + pr] =
                    pack_bf16(acc[mt][j][0] * scale, acc[mt][j][1] * scale);
                stageu[(r0 + 8) * STG_STRIDE + pr] =
                    pack_bf16(acc[mt][j][2] * scale, acc[mt][j][3] * scale);
            }
        }
        __syncthreads();

        if (z != 2) {
#pragma unroll
            for (int i = 0; i < 8; i++) {
                const int c   = t + i * 256;
                const int row = c >> 4;
                const int ch  = c & 15;
                const int col0 = ch * 8;
                uint32_t v[4];
#pragma unroll
                for (int p = 0; p < 4; p++)
                    v[p] = stageu[row * STG_STRIDE + ch * 4 + p];
                const int rowg = bm + row;
                const int bidx = rowg >> 11;
                const int n    = rowg & 2047;
                const int colg = bn + col0;
                const int h    = colg >> 6;
                const int dh   = colg & 63;
                float4* dst = (float4*)&outp[((((size_t)bidx * NH + h) * SEQ) + n) * DH + dh];
                *dst = make_float4(__uint_as_float(v[0]), __uint_as_float(v[1]),
                                   __uint_as_float(v[2]), __uint_as_float(v[3]));
            }
        } else {
#pragma unroll
            for (int i = 0; i < 8; i++) {
                const int c     = t + i * 256;
                const int dhcol = c >> 4;
                const int nch   = c & 15;
                const int n0    = nch * 8;
                const int sh    = (dhcol & 1) * 16;
                const int pcol  = dhcol >> 1;
                uint32_t uv[8];
#pragma unroll
                for (int kk = 0; kk < 8; kk++) {
                    const int k = kk ^ (nch & 7);
                    uv[k] = stageu[(n0 + k) * STG_STRIDE + pcol];
                }
                uint32_t pk[4];
#pragma unroll
                for (int p = 0; p < 4; p++) {
                    const uint32_t v0 = (uv[2 * p]     >> sh) & 0xffffu;
                    const uint32_t v1 = (uv[2 * p + 1] >> sh) & 0xffffu;
                    pk[p] = v0 | (v1 << 16);
                }
                const int rowg = bm + n0;
                const int bidx = rowg >> 11;
                const int n    = rowg & 2047;
                const int colg = bn + dhcol;
                const int h    = colg >> 6;
                const int dh   = colg & 63;
                float4* dst = (float4*)&outp[((((size_t)bidx * NH + h) * DH) + dh) * SEQ + n];
                *dst = make_float4(__uint_as_float(pk[0]), __uint_as_float(pk[1]),
                                   __uint_as_float(pk[2]), __uint_as_float(pk[3]));
            }
        }
    }
}

// ---------------------------------------------------------------------------
// Kernel 2: persistent flash attention (r12-proven version, unchanged)
// ---------------------------------------------------------------------------
#define UKSTRIDE   36
#define KV_STAGE_U (64 * UKSTRIDE)                 // 2304
#define VS_BASE_U  (3 * KV_STAGE_U)                // 6912
#define PS_BASE_U  (VS_BASE_U + 3 * KV_STAGE_U)    // 13824
#define FLASH_SMEM_U (PS_BASE_U + 128 * UKSTRIDE)  // 18432 -> 73728 B
#define FLASH_UNITS (Bb * NH * (SEQ / 128))        // 768

__global__ __launch_bounds__(256, 2) void flash_kernel() {
    extern __shared__ uint32_t smu[];
    const uint32_t su = (uint32_t)__cvta_generic_to_shared(smu);
    uint32_t* Psu = smu + PS_BASE_U;

    const int t  = threadIdx.x;
    const int warp = t >> 5;
    const int lane = t & 31;
    const int qr = lane >> 2;
    const int qc = lane & 3;
    const int wrow = warp * 16;

    const int lm_row = (lane & 7) + ((lane & 16) >> 1);
    const int lm_col = (lane & 8) >> 1;
    const uint32_t lm_off = (uint32_t)(lm_row * UKSTRIDE + lm_col) * 4;

    for (int unit = blockIdx.x; unit < FLASH_UNITS; unit += gridDim.x) {
        __syncthreads();

        const int qt = unit & 15;
        const int bh = unit >> 4;
        const int h  = bh % NH;
        const int b  = bh / NH;

        const size_t head_nd = ((size_t)b * NH + h) * SEQ * DH;
        const __nv_bfloat16* qbase  = g_qb + head_nd + (size_t)qt * 128 * DH;
        const __nv_bfloat16* kbase  = g_kb + head_nd;
        const __nv_bfloat16* vtbase = g_vt + head_nd;

#pragma unroll
        for (int st = 0; st < 2; st++) {
            const __nv_bfloat16* ktile = kbase + (size_t)st * 64 * DH;
            const __nv_bfloat16* vtile = vtbase + (size_t)st * 64;
#pragma unroll
            for (int i = 0; i < 2; i++) {
                const int lin = t + i * 256;
                const int row = lin >> 3;
                const int ch  = lin & 7;
                cp16(su + (uint32_t)(st * KV_STAGE_U + row * UKSTRIDE + ch * 4) * 4,
                     ktile + row * DH + ch * 8);
                cp16(su + (uint32_t)(VS_BASE_U + st * KV_STAGE_U + row * UKSTRIDE + ch * 4) * 4,
                     vtile + (size_t)row * SEQ + ch * 8);
            }
            CP_COMMIT();
        }

#pragma unroll
        for (int i = 0; i < 4; i++) {
            const int lin = t + i * 256;
            const int row = lin >> 3;
            const int ch  = lin & 7;
            *(float4*)&Psu[row * UKSTRIDE + ch * 4] =
                *(const float4*)&qbase[row * DH + ch * 8];
        }
        __syncthreads();

        uint32_t qf[4][4];
#pragma unroll
        for (int ks = 0; ks < 4; ks++) {
            qf[ks][0] = Psu[(wrow + qr) * UKSTRIDE + ks * 8 + qc];
            qf[ks][1] = Psu[(wrow + qr + 8) * UKSTRIDE + ks * 8 + qc];
            qf[ks][2] = Psu[(wrow + qr) * UKSTRIDE + ks * 8 + 4 + qc];
            qf[ks][3] = Psu[(wrow + qr + 8) * UKSTRIDE + ks * 8 + 4 + qc];
        }

        float o[8][4];
#pragma unroll
        for (int j = 0; j < 8; j++)
#pragma unroll
            for (int e = 0; e < 4; e++) o[j][e] = 0.0f;
        float m_lo = -INFINITY, m_hi = -INFINITY, l_lo = 0.0f, l_hi = 0.0f;

        int cs = 0, fs = 2;
        for (int kt = 0; kt < SEQ / 64; kt++) {
            if (kt + 1 < SEQ / 64) { CP_WAIT1(); } else { CP_WAIT0(); }
            __syncthreads();
            if (kt + 2 < SEQ / 64) {
                const __nv_bfloat16* ktile = kbase + (size_t)(kt + 2) * 64 * DH;
                const __nv_bfloat16* vtile = vtbase + (size_t)(kt + 2) * 64;
#pragma unroll
                for (int i = 0; i < 2; i++) {
                    const int lin = t + i * 256;
                    const int row = lin >> 3;
                    const int ch  = lin & 7;
                    cp16(su + (uint32_t)(fs * KV_STAGE_U + row * UKSTRIDE + ch * 4) * 4,
                         ktile + row * DH + ch * 8);
                    cp16(su + (uint32_t)(VS_BASE_U + fs * KV_STAGE_U + row * UKSTRIDE + ch * 4) * 4,
                         vtile + (size_t)row * SEQ + ch * 8);
                }
                CP_COMMIT();
            }

            const uint32_t k_lm = su + (uint32_t)(cs * KV_STAGE_U) * 4 + lm_off;
            const uint32_t v_lm = su + (uint32_t)(VS_BASE_U + cs * KV_STAGE_U) * 4 + lm_off;

            float s[8][4];
#pragma unroll
            for (int j = 0; j < 8; j++)
#pragma unroll
                for (int e = 0; e < 4; e++) s[j][e] = 0.0f;
#pragma unroll
            for (int ks = 0; ks < 4; ks++) {
#pragma unroll
                for (int jp = 0; jp < 4; jp++) {
                    uint32_t b0, b1, b2, b3;
                    ldmatrix_x4(b0, b1, b2, b3,
                                k_lm + (uint32_t)(jp * 16 * UKSTRIDE + ks * 8) * 4);
                    uint32_t br0[2] = {b0, b1};
                    uint32_t br1[2] = {b2, b3};
                    mma_bf16(s[2 * jp],     qf[ks], br0);
                    mma_bf16(s[2 * jp + 1], qf[ks], br1);
                }
            }

            float mx_lo = m_lo, mx_hi = m_hi;
#pragma unroll
            for (int j = 0; j < 8; j++) {
                mx_lo = fmaxf(mx_lo, fmaxf(s[j][0], s[j][1]));
                mx_hi = fmaxf(mx_hi, fmaxf(s[j][2], s[j][3]));
            }
            mx_lo = fmaxf(mx_lo, __shfl_xor_sync(0xffffffffu, mx_lo, 1));
            mx_lo = fmaxf(mx_lo, __shfl_xor_sync(0xffffffffu, mx_lo, 2));
            mx_hi = fmaxf(mx_hi, __shfl_xor_sync(0xffffffffu, mx_hi, 1));
            mx_hi = fmaxf(mx_hi, __shfl_xor_sync(0xffffffffu, mx_hi, 2));

            const float c_lo = exp2f(m_lo - mx_lo);
            const float c_hi = exp2f(m_hi - mx_hi);
            float sum_lo = 0.0f, sum_hi = 0.0f;
#pragma unroll
            for (int j = 0; j < 8; j++) {
                s[j][0] = exp2f(s[j][0] - mx_lo);
                s[j][1] = exp2f(s[j][1] - mx_lo);
                s[j][2] = exp2f(s[j][2] - mx_hi);
                s[j][3] = exp2f(s[j][3] - mx_hi);
                sum_lo += s[j][0] + s[j][1];
                sum_hi += s[j][2] + s[j][3];
            }
            sum_lo += __shfl_xor_sync(0xffffffffu, sum_lo, 1);
            sum_lo += __shfl_xor_sync(0xffffffffu, sum_lo, 2);
            sum_hi += __shfl_xor_sync(0xffffffffu, sum_hi, 1);
            sum_hi += __shfl_xor_sync(0xffffffffu, sum_hi, 2);
            l_lo = l_lo * c_lo + sum_lo;
            l_hi = l_hi * c_hi + sum_hi;
            m_lo = mx_lo;
            m_hi = mx_hi;

#pragma unroll
            for (int j = 0; j < 8; j++) {
                o[j][0] *= c_lo; o[j][1] *= c_lo;
                o[j][2] *= c_hi; o[j][3] *= c_hi;
            }

#pragma unroll
            for (int ks = 0; ks < 4; ks++) {
                uint32_t a[4];
                a[0] = pack_bf16(s[2 * ks][0],     s[2 * ks][1]);
                a[1] = pack_bf16(s[2 * ks][2],     s[2 * ks][3]);
                a[2] = pack_bf16(s[2 * ks + 1][0], s[2 * ks + 1][1]);
                a[3] = pack_bf16(s[2 * ks + 1][2], s[2 * ks + 1][3]);
#pragma unroll
                for (int jp = 0; jp < 4; jp++) {
                    uint32_t b0, b1, b2, b3;
                    ldmatrix_x4(b0, b1, b2, b3,
                                v_lm + (uint32_t)(jp * 16 * UKSTRIDE + ks * 8) * 4);
                    uint32_t br0[2] = {b0, b1};
                    uint32_t br1[2] = {b2, b3};
                    mma_bf16(o[2 * jp],     a, br0);
                    mma_bf16(o[2 * jp + 1], a, br1);
                }
            }

            cs = (cs == 2) ? 0 : cs + 1;
            fs = (fs == 2) ? 0 : fs + 1;
        }

        const float inv_lo = 1.0f / l_lo;
        const float inv_hi = 1.0f / l_hi;
        const int n_lo = qt * 128 + wrow + qr;
#pragma unroll
        for (int j = 0; j < 8; j++) {
            const int col = h * 64 + j * 8 + 2 * qc;
            *(float2*)&g_att[((size_t)b * SEQ + n_lo) * INNER + col] =
                make_float2(tf32r(o[j][0] * inv_lo), tf32r(o[j][1] * inv_lo));
            *(float2*)&g_att[((size_t)b * SEQ + n_lo + 8) * INNER + col] =
                make_float2(tf32r(o[j][2] * inv_hi), tf32r(o[j][3] * inv_hi));
        }
    }
}

// ---------------------------------------------------------------------------
// Kernel 3: output projection (BM=128 x BN=128, ldmatrix frags).
// out = g_att @ Wp + bp  (B = WpT from g_wT[3])
// ---------------------------------------------------------------------------
__global__ __launch_bounds__(256, 2) void proj_kernel(const float* __restrict__ bp,
                                                      float* __restrict__ out) {
    extern __shared__ float smf[];
    const uint32_t su = (uint32_t)__cvta_generic_to_shared(smf);
    const float* WT = g_wT + 3 * (size_t)NWF;

    const int bm = blockIdx.y * 128;
    const int bn = blockIdx.x * 128;
    const int t  = threadIdx.x;
    const int warp = t >> 5;
    const int lane = t & 31;
    const int m_base = (warp >> 1) * 32;
    const int n_base = (warp & 1) * 64;
    const int qr = lane >> 2;
    const int qc = lane & 3;
    const uint32_t a_off = a_lane_off(lane);
    const uint32_t b_off = b_lane_off(lane);

    float acc[2][8][4];
#pragma unroll
    for (int mt = 0; mt < 2; mt++)
#pragma unroll
        for (int j = 0; j < 8; j++)
#pragma unroll
            for (int e = 0; e < 4; e++) acc[mt][j][e] = 0.0f;

    gemm_fill(su, 0, 0, g_att, bm, WT, bn, t);
    CP_COMMIT();
    gemm_fill(su, 1, 32, g_att, bm, WT, bn, t);
    CP_COMMIT();

    int cs = 0, fs = 2;
    for (int kt = 0; kt < INNER / 32; kt++) {
        if (kt + 1 < INNER / 32) { CP_WAIT1(); } else { CP_WAIT0(); }
        __syncthreads();
        if (kt + 2 < INNER / 32) {
            gemm_fill(su, fs, (kt + 2) * 32, g_att, bm, WT, bn, t);
            CP_COMMIT();
        }
        gemm_compute(su, cs, m_base, n_base, a_off, b_off, acc);
        cs = (cs == 2) ? 0 : cs + 1;
        fs = (fs == 2) ? 0 : fs + 1;
    }

#pragma unroll
    for (int mt = 0; mt < 2; mt++) {
#pragma unroll
        for (int j = 0; j < 8; j++) {
            const int row0 = bm + m_base + mt * 16 + qr;
            const int col0 = bn + n_base + j * 8 + 2 * qc;
            out[(size_t)row0 * DIM + col0]           = acc[mt][j][0] + bp[col0];
            out[(size_t)row0 * DIM + col0 + 1]       = acc[mt][j][1] + bp[col0 + 1];
            out[(size_t)(row0 + 8) * DIM + col0]     = acc[mt][j][2] + bp[col0];
            out[(size_t)(row0 + 8) * DIM + col0 + 1] = acc[mt][j][3] + bp[col0 + 1];
        }
    }
}

// ---------------------------------------------------------------------------
extern "C" void kernel_launch(void* const* d_in, const int* in_sizes, int n_in,
                              void* d_out, int out_size) {
    const float* x  = (const float*)d_in[0];
    const float* Wq = (const float*)d_in[1];
    const float* Wk = (const float*)d_in[2];
    const float* Wv = (const float*)d_in[3];
    const float* Wp = (const float*)d_in[4];
    const float* bp = (const float*)d_in[5];
    float* out = (float*)d_out;

    int dev = 0, sms = 148;
    cudaGetDevice(&dev);
    cudaDeviceGetAttribute(&sms, cudaDevAttrMultiProcessorCount, dev);
    const int slots = 2 * sms;

    const int gemm_smem  = GEMM_SMEM_FLOATS * (int)sizeof(float);   // 110592
    const int flash_smem = FLASH_SMEM_U * (int)sizeof(uint32_t);    // 73728
    cudaFuncSetAttribute(qkv_kernel,
                         cudaFuncAttributeMaxDynamicSharedMemorySize, gemm_smem);
    cudaFuncSetAttribute(flash_kernel,
                         cudaFuncAttributeMaxDynamicSharedMemorySize, flash_smem);
    cudaFuncSetAttribute(proj_kernel,
                         cudaFuncAttributeMaxDynamicSharedMemorySize, gemm_smem);

    // 0) round + transpose weights (tiled, coalesced)
    round_kernel<<<dim3(INNER / 32, DIM / 32, 4), 256>>>(Wq, Wk, Wv, Wp);

    // 1) QKV projections (persistent, ldmatrix frags)
    const int g1 = (QKV_UNITS < slots) ? QKV_UNITS : slots;
    qkv_kernel<<<g1, 256, gemm_smem>>>(x);

    // 2) flash attention (persistent)
    const int g2 = (FLASH_UNITS < slots) ? FLASH_UNITS : slots;
    flash_kernel<<<g2, 256, flash_smem>>>();

    // 3) output projection + bias
    proj_kernel<<<dim3(DIM / 128, MROWS / 128), 256, gemm_smem>>>(bp, out);
}